// round 15
// baseline (speedup 1.0000x reference)
#include <cuda_runtime.h>

// CharRNN: 3-layer tanh RNN, B=512, T=1024, HID=100, VOCAB=62.
// R15: R14 champion with doubled latency hiding:
//      512 threads (16 warps -> 4 per SMSP, was 2), 4-way k-split
//      (group g = tid>>7 owns a k-quarter; kc 7/6/6/6).
//      Scratch exchange generalized: sc[layer][row][group][128]; group g
//      sends partials for rows != g and FINALIZES row g only -> epilogue
//      3 tanho/thread (was 6), 1 table LDG (was 2). Same 2 barriers/tick,
//      same fused 3-layer dot, same cross-warp scratch mechanism.
//      Decoder + table kernels unchanged.

#define BB    512
#define TT    1024
#define HID   100
#define VOCAB 62
#define NL    3
#define ROWS  4
#define NCTA  (BB / ROWS)       // 128
#define NTHR  512               // 16 warps, 4 per SMSP

// ---- shared memory layout (floats) ----
#define OFF_WH1  0
#define OFF_WI2  10000
#define OFF_WH2  20000
#define OFF_WI3  30000
#define OFF_WH3  40000
#define OFF_SCR  50000          // [layer][row][group][128] = 3*4*4*128 = 6144
#define OFF_H1   56144          // 4x100  (single buffer, in-place)
#define OFF_H2   56544
#define OFF_H3   56944
#define SMEM_FLOATS 57344       // 229,376 bytes

typedef unsigned long long ull;

__device__ float g_table[VOCAB * HID];            // emb@Wi1^T + b_ih1 + b_hh1
__device__ float g_h3[(size_t)BB * TT * HID];     // h3 stream (200 MB)

// ---------------------------------------------------------------------------
__global__ void table_kernel(const float* __restrict__ emb,
                             const float* __restrict__ W_ih,
                             const float* __restrict__ b_ih,
                             const float* __restrict__ b_hh) {
    int v = blockIdx.x;
    int j = threadIdx.x;
    if (j >= HID) return;
    float acc = b_ih[j] + b_hh[j];
    const float* e = emb + v * HID;
    const float* w = W_ih + j * HID;
#pragma unroll
    for (int k = 0; k < HID; k++) acc += e[k] * w[k];
    g_table[v * HID + j] = acc;
}

// ---------------------------------------------------------------------------
__device__ __forceinline__ void fma2(ull& acc, ull a, ull b) {
    asm("fma.rn.f32x2 %0, %1, %2, %3;" : "=l"(acc) : "l"(a), "l"(b), "l"(acc));
}
__device__ __forceinline__ float hadd2(ull a) {
    float lo = __uint_as_float((unsigned)a);
    float hi = __uint_as_float((unsigned)(a >> 32));
    return lo + hi;
}
__device__ __forceinline__ ulonglong2 ldv(const float* pf) {
    return *reinterpret_cast<const ulonglong2*>(pf);
}
__device__ __forceinline__ float tanho(float x) {
    float e = __expf(2.0f * x);
    return 1.0f - __fdividef(2.0f, e + 1.0f);
}

// fused 3-layer partial dot over quad range [KB,KE):
//   a1[r] += wh1 . h1_r ; a2[r] += wi2 . h1_r + wh2 . h2_r
//   a3[r] += wi3 . h2_r + wh3 . h3_r
template <int KB, int KE>
__device__ __forceinline__ void dotF(const float* __restrict__ wh1row,
                                     const float* __restrict__ wi2row,
                                     const float* __restrict__ wh2row,
                                     const float* __restrict__ wi3row,
                                     const float* __restrict__ wh3row,
                                     const float* __restrict__ h1b,
                                     const float* __restrict__ h2b,
                                     const float* __restrict__ h3b,
                                     ull a1[ROWS], ull a2[ROWS], ull a3[ROWS]) {
#pragma unroll
    for (int kc = KB; kc < KE; kc++) {
        ulonglong2 w1 = ldv(wh1row + kc * 4);
        ulonglong2 wi = ldv(wi2row + kc * 4);
        ulonglong2 wh = ldv(wh2row + kc * 4);
        ulonglong2 vi = ldv(wi3row + kc * 4);
        ulonglong2 vh = ldv(wh3row + kc * 4);
#pragma unroll
        for (int r = 0; r < ROWS; r++) {
            ulonglong2 h1 = ldv(h1b + r * HID + kc * 4);
            ulonglong2 h2 = ldv(h2b + r * HID + kc * 4);
            ulonglong2 h3 = ldv(h3b + r * HID + kc * 4);
            fma2(a1[r], w1.x, h1.x); fma2(a1[r], w1.y, h1.y);
            fma2(a2[r], wi.x, h1.x); fma2(a2[r], wi.y, h1.y);
            fma2(a2[r], wh.x, h2.x); fma2(a2[r], wh.y, h2.y);
            fma2(a3[r], vi.x, h2.x); fma2(a3[r], vi.y, h2.y);
            fma2(a3[r], vh.x, h3.x); fma2(a3[r], vh.y, h3.y);
        }
    }
}

// ---------------------------------------------------------------------------
__global__ __launch_bounds__(NTHR, 1)
void rnn_kernel(const int*   __restrict__ ids,
                const float* __restrict__ W_ih,
                const float* __restrict__ W_hh,
                const float* __restrict__ b_ih,
                const float* __restrict__ b_hh,
                float* __restrict__ hidden) {
    extern __shared__ float s[];
    const int tid = threadIdx.x;
    const int g   = tid >> 7;        // k-quarter group 0..3; also MY row
    const int j   = tid & 127;       // neuron index
    const int b0  = blockIdx.x * ROWS;
    const bool act = (j < HID);
    const int jc  = act ? j : (HID - 1);

    // ---- stage weights + zero h buffers ----
    for (int i = tid; i < HID * HID; i += NTHR) {
        s[OFF_WH1 + i] = W_hh[i];
        s[OFF_WI2 + i] = W_ih[1 * HID * HID + i];
        s[OFF_WH2 + i] = W_hh[1 * HID * HID + i];
        s[OFF_WI3 + i] = W_ih[2 * HID * HID + i];
        s[OFF_WH3 + i] = W_hh[2 * HID * HID + i];
    }
    for (int i = tid; i < ROWS * HID; i += NTHR) {
        s[OFF_H2 + i] = 0.0f;
        s[OFF_H3 + i] = 0.0f;
    }

    const float rb2 = b_ih[1 * HID + jc] + b_hh[1 * HID + jc];
    const float rb3 = b_ih[2 * HID + jc] + b_hh[2 * HID + jc];

    const float* wh1 = s + OFF_WH1 + jc * HID;
    const float* wi2 = s + OFF_WI2 + jc * HID;
    const float* wh2 = s + OFF_WH2 + jc * HID;
    const float* wi3 = s + OFF_WI3 + jc * HID;
    const float* wh3 = s + OFF_WH3 + jc * HID;

    __syncthreads();   // weights/zeros ordered before h1(0) writes (R13 race class)

    // ---- pre-loop: h1(0) = tanh(table[tok(0)]) — group g writes row g ----
    if (act) {
        int t0 = ids[(b0 + g) * TT];
        s[OFF_H1 + g * HID + j] = tanho(g_table[t0 * HID + j]);
    }
    // token for row g at time 1 (consumed as tbl at tick 0)
    int tok = ids[(b0 + g) * TT + ((TT > 1) ? 1 : 0)];
    __syncthreads();

    // ======================= pipelined tick loop =======================
    // tick u: h1(u+1) [u<=TT-2], h2(u) [u<=TT-1], h3(u-1) [u>=1]
    for (int u = 0; u <= TT; u++) {
        // long-latency loads first (hidden under the dot)
        const float tbl = g_table[tok * HID + jc];
        const int tn = (u + 2 <= TT - 1) ? (u + 2) : (TT - 1);
        const int ntok = ids[(b0 + g) * TT + tn];

        ull a1[ROWS] = {0, 0, 0, 0};
        ull a2[ROWS] = {0, 0, 0, 0};
        ull a3[ROWS] = {0, 0, 0, 0};
        if (act) {
            if (g == 0)
                dotF<0, 7>(wh1, wi2, wh2, wi3, wh3,
                           s + OFF_H1, s + OFF_H2, s + OFF_H3, a1, a2, a3);
            else if (g == 1)
                dotF<7, 13>(wh1, wi2, wh2, wi3, wh3,
                            s + OFF_H1, s + OFF_H2, s + OFF_H3, a1, a2, a3);
            else if (g == 2)
                dotF<13, 19>(wh1, wi2, wh2, wi3, wh3,
                             s + OFF_H1, s + OFF_H2, s + OFF_H3, a1, a2, a3);
            else
                dotF<19, 25>(wh1, wi2, wh2, wi3, wh3,
                             s + OFF_H1, s + OFF_H2, s + OFF_H3, a1, a2, a3);
        }
        float v1[ROWS], v2[ROWS], v3[ROWS];
#pragma unroll
        for (int r = 0; r < ROWS; r++) {
            v1[r] = hadd2(a1[r]); v2[r] = hadd2(a2[r]); v3[r] = hadd2(a3[r]);
        }

        // exchange: send partials for rows I don't own; layout [l][r][g][128]
        if (act) {
#pragma unroll
            for (int r = 0; r < ROWS; r++) {
                if (r != g) {
                    s[OFF_SCR + ((0 * 4 + r) * 4 + g) * 128 + j] = v1[r];
                    s[OFF_SCR + ((1 * 4 + r) * 4 + g) * 128 + j] = v2[r];
                    s[OFF_SCR + ((2 * 4 + r) * 4 + g) * 128 + j] = v3[r];
                }
            }
        }
        __syncthreads();

        if (act) {
            float s1 = v1[g], s2 = v2[g], s3 = v3[g];
#pragma unroll
            for (int gp = 0; gp < 4; gp++) {
                if (gp != g) {
                    s1 += s[OFF_SCR + ((0 * 4 + g) * 4 + gp) * 128 + j];
                    s2 += s[OFF_SCR + ((1 * 4 + g) * 4 + gp) * 128 + j];
                    s3 += s[OFF_SCR + ((2 * 4 + g) * 4 + gp) * 128 + j];
                }
            }
            if (u + 1 <= TT - 1)            // h1(u+1), row g
                s[OFF_H1 + g * HID + j] = tanho(tbl + s1);
            if (u <= TT - 1)                // h2(u), row g
                s[OFF_H2 + g * HID + j] = tanho(rb2 + s2);
            if (u >= 1) {                   // h3(u-1), row g + stream-out
                float q = tanho(rb3 + s3);
                s[OFF_H3 + g * HID + j] = q;
                g_h3[((size_t)(b0 + g) * TT + (u - 1)) * HID + j] = q;
            }
        }
        tok = ntok;
        __syncthreads();
    }

    // ---- final hidden [NL, B, HID]: buffers hold h(TT-1) for all layers ----
    for (int i = tid; i < NL * ROWS * HID; i += NTHR) {
        const int l = i / (ROWS * HID);
        const int rem = i - l * (ROWS * HID);
        const int r = rem / HID;
        const int jj = rem - r * HID;
        hidden[(size_t)(l * BB + b0 + r) * HID + jj] =
            s[OFF_H1 + l * 400 + r * HID + jj];
    }
}

// ---------------------------------------------------------------------------
// Decoder GEMM (unchanged from R12/R14)
// ---------------------------------------------------------------------------
#define DT   256
#define GR   128
#define DS_W 0
#define DS_H 6208
#define DS_B 19008
#define DS_FLOATS 19072

__global__ __launch_bounds__(DT)
void dec_kernel(const float* __restrict__ W_dec,
                const float* __restrict__ b_dec,
                float* __restrict__ logits) {
    extern __shared__ float ds[];
    const int tid  = threadIdx.x;
    const int tile = blockIdx.x;

    float4* sw4 = reinterpret_cast<float4*>(ds + DS_W);
    const float4* wsrc = reinterpret_cast<const float4*>(W_dec);
    for (int i = tid; i < VOCAB * HID / 4; i += DT) sw4[i] = wsrc[i];

    float4* sh4 = reinterpret_cast<float4*>(ds + DS_H);
    const float4* hsrc = reinterpret_cast<const float4*>(g_h3 + (size_t)tile * GR * HID);
    for (int i = tid; i < GR * HID / 4; i += DT) sh4[i] = hsrc[i];

    for (int i = tid; i < VOCAB; i += DT) ds[DS_B + i] = b_dec[i];
    __syncthreads();

    const int r    = tid & 127;
    const int half = tid >> 7;
    const int jb   = half * 31;

    ull acc[31];
#pragma unroll
    for (int jj = 0; jj < 31; jj++) acc[jj] = 0ull;

    const float* hrow = ds + DS_H + r * HID;
    for (int kc = 0; kc < 25; kc++) {
        ulonglong2 hq = ldv(hrow + 4 * kc);
#pragma unroll
        for (int jj = 0; jj < 31; jj++) {
            ulonglong2 wq = ldv(ds + DS_W + (jb + jj) * HID + 4 * kc);
            fma2(acc[jj], wq.x, hq.x);
            fma2(acc[jj], wq.y, hq.y);
        }
    }

    float* out = logits + ((size_t)tile * GR + r) * VOCAB + jb;
#pragma unroll
    for (int jj = 0; jj < 31; jj++)
        out[jj] = ds[DS_B + jb + jj] + hadd2(acc[jj]);
}

// ---------------------------------------------------------------------------
extern "C" void kernel_launch(void* const* d_in, const int* in_sizes, int n_in,
                              void* d_out, int out_size) {
    const int*   ids   = (const int*)  d_in[0];
    const float* emb   = (const float*)d_in[1];
    const float* W_ih  = (const float*)d_in[2];
    const float* W_hh  = (const float*)d_in[3];
    const float* b_ih  = (const float*)d_in[4];
    const float* b_hh  = (const float*)d_in[5];
    const float* W_dec = (const float*)d_in[6];
    const float* b_dec = (const float*)d_in[7];

    float* out    = (float*)d_out;
    float* logits = out;
    float* hidden = out + ((size_t)out_size - (size_t)NL * BB * HID);

    table_kernel<<<VOCAB, 128>>>(emb, W_ih, b_ih, b_hh);

    size_t smem = SMEM_FLOATS * sizeof(float);
    cudaFuncSetAttribute(rnn_kernel, cudaFuncAttributeMaxDynamicSharedMemorySize,
                         (int)smem);
    rnn_kernel<<<NCTA, NTHR, smem>>>(ids, W_ih, W_hh, b_ih, b_hh, hidden);

    size_t dsmem = DS_FLOATS * sizeof(float);
    cudaFuncSetAttribute(dec_kernel, cudaFuncAttributeMaxDynamicSharedMemorySize,
                         (int)dsmem);
    dec_kernel<<<(BB * TT) / GR, DT, dsmem>>>(W_dec, b_dec, logits);
}

// round 16
// speedup vs baseline: 1.0279x; 1.0279x over previous
#include <cuda_runtime.h>

// CharRNN: 3-layer tanh RNN, B=512, T=1024, HID=100, VOCAB=62.
// R16: R14 champion + perfect k-split balance:
//      p0: quads 0..11 + lower half-pair of quad 12 (LDS.64 @ +48)
//      p1: upper half-pair of quad 12 (LDS.64 @ +50) + quads 13..24
//      -> both groups do exactly 12.5 kc (R14: 13 vs 12, p0 paced the CTA).
//      Plus: g_h3 STG issued before smem stores in epilogue.
//      Everything else identical to R14 (scratch exchange, 2 barriers/tick,
//      pipelined tick = h1(u+1),h2(u),h3(u-1), decoder offloaded).

#define BB    512
#define TT    1024
#define HID   100
#define VOCAB 62
#define NL    3
#define ROWS  4
#define NCTA  (BB / ROWS)       // 128
#define NTHR  256

// ---- shared memory layout (floats) ----
#define OFF_WH1  0
#define OFF_WI2  10000
#define OFF_WH2  20000
#define OFF_WI3  30000
#define OFF_WH3  40000
#define OFF_SCR  50000          // [group][layer][256]: 2*3*256 = 1536
#define OFF_H1   51536          // 4x100  (single buffer, in-place)
#define OFF_H2   51936
#define OFF_H3   52336
#define SMEM_FLOATS 52736       // 210,944 bytes

typedef unsigned long long ull;

__device__ float g_table[VOCAB * HID];            // emb@Wi1^T + b_ih1 + b_hh1
__device__ float g_h3[(size_t)BB * TT * HID];     // h3 stream (200 MB)

// ---------------------------------------------------------------------------
__global__ void table_kernel(const float* __restrict__ emb,
                             const float* __restrict__ W_ih,
                             const float* __restrict__ b_ih,
                             const float* __restrict__ b_hh) {
    int v = blockIdx.x;
    int j = threadIdx.x;
    if (j >= HID) return;
    float acc = b_ih[j] + b_hh[j];
    const float* e = emb + v * HID;
    const float* w = W_ih + j * HID;
#pragma unroll
    for (int k = 0; k < HID; k++) acc += e[k] * w[k];
    g_table[v * HID + j] = acc;
}

// ---------------------------------------------------------------------------
__device__ __forceinline__ void fma2(ull& acc, ull a, ull b) {
    asm("fma.rn.f32x2 %0, %1, %2, %3;" : "=l"(acc) : "l"(a), "l"(b), "l"(acc));
}
__device__ __forceinline__ float hadd2(ull a) {
    float lo = __uint_as_float((unsigned)a);
    float hi = __uint_as_float((unsigned)(a >> 32));
    return lo + hi;
}
__device__ __forceinline__ ulonglong2 ldv(const float* pf) {
    return *reinterpret_cast<const ulonglong2*>(pf);
}
__device__ __forceinline__ ull ldp(const float* pf) {   // 8B pair load
    return *reinterpret_cast<const ull*>(pf);
}
__device__ __forceinline__ float tanho(float x) {
    float e = __expf(2.0f * x);
    return 1.0f - __fdividef(2.0f, e + 1.0f);
}

// fused 3-layer partial dot over quad range [KB,KE):
//   a1[r] += wh1 . h1_r ; a2[r] += wi2 . h1_r + wh2 . h2_r
//   a3[r] += wi3 . h2_r + wh3 . h3_r
template <int KB, int KE>
__device__ __forceinline__ void dotF(const float* __restrict__ wh1row,
                                     const float* __restrict__ wi2row,
                                     const float* __restrict__ wh2row,
                                     const float* __restrict__ wi3row,
                                     const float* __restrict__ wh3row,
                                     const float* __restrict__ h1b,
                                     const float* __restrict__ h2b,
                                     const float* __restrict__ h3b,
                                     ull a1[ROWS], ull a2[ROWS], ull a3[ROWS]) {
#pragma unroll
    for (int kc = KB; kc < KE; kc++) {
        ulonglong2 w1 = ldv(wh1row + kc * 4);
        ulonglong2 wi = ldv(wi2row + kc * 4);
        ulonglong2 wh = ldv(wh2row + kc * 4);
        ulonglong2 vi = ldv(wi3row + kc * 4);
        ulonglong2 vh = ldv(wh3row + kc * 4);
#pragma unroll
        for (int r = 0; r < ROWS; r++) {
            ulonglong2 h1 = ldv(h1b + r * HID + kc * 4);
            ulonglong2 h2 = ldv(h2b + r * HID + kc * 4);
            ulonglong2 h3 = ldv(h3b + r * HID + kc * 4);
            fma2(a1[r], w1.x, h1.x); fma2(a1[r], w1.y, h1.y);
            fma2(a2[r], wi.x, h1.x); fma2(a2[r], wi.y, h1.y);
            fma2(a2[r], wh.x, h2.x); fma2(a2[r], wh.y, h2.y);
            fma2(a3[r], vi.x, h2.x); fma2(a3[r], vi.y, h2.y);
            fma2(a3[r], vh.x, h3.x); fma2(a3[r], vh.y, h3.y);
        }
    }
}

// middle half-quad (one f32 pair at float offset OFF: 48 for p0, 50 for p1)
__device__ __forceinline__ void dotM(const float* __restrict__ wh1row,
                                     const float* __restrict__ wi2row,
                                     const float* __restrict__ wh2row,
                                     const float* __restrict__ wi3row,
                                     const float* __restrict__ wh3row,
                                     const float* __restrict__ h1b,
                                     const float* __restrict__ h2b,
                                     const float* __restrict__ h3b,
                                     int off,
                                     ull a1[ROWS], ull a2[ROWS], ull a3[ROWS]) {
    ull w1 = ldp(wh1row + off);
    ull wi = ldp(wi2row + off);
    ull wh = ldp(wh2row + off);
    ull vi = ldp(wi3row + off);
    ull vh = ldp(wh3row + off);
#pragma unroll
    for (int r = 0; r < ROWS; r++) {
        ull h1 = ldp(h1b + r * HID + off);
        ull h2 = ldp(h2b + r * HID + off);
        ull h3 = ldp(h3b + r * HID + off);
        fma2(a1[r], w1, h1);
        fma2(a2[r], wi, h1); fma2(a2[r], wh, h2);
        fma2(a3[r], vi, h2); fma2(a3[r], vh, h3);
    }
}

// ---------------------------------------------------------------------------
__global__ __launch_bounds__(NTHR, 1)
void rnn_kernel(const int*   __restrict__ ids,
                const float* __restrict__ W_ih,
                const float* __restrict__ W_hh,
                const float* __restrict__ b_ih,
                const float* __restrict__ b_hh,
                float* __restrict__ hidden) {
    extern __shared__ float s[];
    const int tid = threadIdx.x;
    const int p   = tid >> 7;        // k-split group: 0 or 1
    const int j   = tid & 127;       // neuron index
    const int b0  = blockIdx.x * ROWS;
    const bool act = (j < HID);
    const int jc  = act ? j : (HID - 1);
    const int r0  = 2 * p;           // rows I finalize: r0, r0+1
    const int r1  = r0 + 1;
    const int so  = 2 - 2 * p;       // rows I send (other group's rows)

    // ---- stage weights + zero h buffers ----
    for (int i = tid; i < HID * HID; i += NTHR) {
        s[OFF_WH1 + i] = W_hh[i];
        s[OFF_WI2 + i] = W_ih[1 * HID * HID + i];
        s[OFF_WH2 + i] = W_hh[1 * HID * HID + i];
        s[OFF_WI3 + i] = W_ih[2 * HID * HID + i];
        s[OFF_WH3 + i] = W_hh[2 * HID * HID + i];
    }
    for (int i = tid; i < ROWS * HID; i += NTHR) {
        s[OFF_H1 + i] = 0.0f;
        s[OFF_H2 + i] = 0.0f;
        s[OFF_H3 + i] = 0.0f;
    }

    const float rb2 = b_ih[1 * HID + jc] + b_hh[1 * HID + jc];
    const float rb3 = b_ih[2 * HID + jc] + b_hh[2 * HID + jc];

    const float* wh1 = s + OFF_WH1 + jc * HID;
    const float* wi2 = s + OFF_WI2 + jc * HID;
    const float* wh2 = s + OFF_WH2 + jc * HID;
    const float* wi3 = s + OFF_WI3 + jc * HID;
    const float* wh3 = s + OFF_WH3 + jc * HID;

    // order zero-init before h1(0) writes (R13 race class)
    __syncthreads();

    // ---- pre-loop: h1(0) = tanh(table[tok(0)]) ----
    if (p == 0 && act) {
#pragma unroll
        for (int r = 0; r < ROWS; r++) {
            int t0 = ids[(b0 + r) * TT];
            s[OFF_H1 + r * HID + j] = tanho(g_table[t0 * HID + j]);
        }
    }
    // tokens for time 1 (my finalize rows only)
    int tokA = ids[(b0 + r0) * TT + ((TT > 1) ? 1 : 0)];
    int tokB = ids[(b0 + r1) * TT + ((TT > 1) ? 1 : 0)];
    __syncthreads();

    // ======================= pipelined tick loop =======================
    // tick u: h1(u+1) [u<=TT-2], h2(u) [u<=TT-1], h3(u-1) [u>=1]
    for (int u = 0; u <= TT; u++) {
        // long-latency loads first (hidden under the dot)
        const float tblA = g_table[tokA * HID + jc];
        const float tblB = g_table[tokB * HID + jc];
        const int tn = (u + 2 <= TT - 1) ? (u + 2) : (TT - 1);
        const int nA = ids[(b0 + r0) * TT + tn];
        const int nB = ids[(b0 + r1) * TT + tn];

        ull a1[ROWS] = {0, 0, 0, 0};
        ull a2[ROWS] = {0, 0, 0, 0};
        ull a3[ROWS] = {0, 0, 0, 0};
        if (act) {
            if (p == 0) {
                dotF<0, 12>(wh1, wi2, wh2, wi3, wh3,
                            s + OFF_H1, s + OFF_H2, s + OFF_H3, a1, a2, a3);
                dotM(wh1, wi2, wh2, wi3, wh3,
                     s + OFF_H1, s + OFF_H2, s + OFF_H3, 48, a1, a2, a3);
            } else {
                dotM(wh1, wi2, wh2, wi3, wh3,
                     s + OFF_H1, s + OFF_H2, s + OFF_H3, 50, a1, a2, a3);
                dotF<13, 25>(wh1, wi2, wh2, wi3, wh3,
                             s + OFF_H1, s + OFF_H2, s + OFF_H3, a1, a2, a3);
            }
        }
        float v1[ROWS], v2[ROWS], v3[ROWS];
#pragma unroll
        for (int r = 0; r < ROWS; r++) {
            v1[r] = hadd2(a1[r]); v2[r] = hadd2(a2[r]); v3[r] = hadd2(a3[r]);
        }

        // exchange: send my partials for the OTHER group's rows (so, so+1)
        if (act) {
            float* sc = s + OFF_SCR + p * 768;
            *reinterpret_cast<float2*>(&sc[0 * 256 + 2 * j]) = make_float2(v1[so], v1[so + 1]);
            *reinterpret_cast<float2*>(&sc[1 * 256 + 2 * j]) = make_float2(v2[so], v2[so + 1]);
            *reinterpret_cast<float2*>(&sc[2 * 256 + 2 * j]) = make_float2(v3[so], v3[so + 1]);
        }
        __syncthreads();

        if (act) {
            const float* oc = s + OFF_SCR + (1 - p) * 768;
            float2 o1 = *reinterpret_cast<const float2*>(&oc[0 * 256 + 2 * j]);
            float2 o2 = *reinterpret_cast<const float2*>(&oc[1 * 256 + 2 * j]);
            float2 o3 = *reinterpret_cast<const float2*>(&oc[2 * 256 + 2 * j]);

            if (u >= 1) {                   // h3(u-1): STG first (independent)
                float q0 = tanho(rb3 + v3[r0] + o3.x);
                float q1 = tanho(rb3 + v3[r1] + o3.y);
                g_h3[((size_t)(b0 + r0) * TT + (u - 1)) * HID + j] = q0;
                g_h3[((size_t)(b0 + r1) * TT + (u - 1)) * HID + j] = q1;
                s[OFF_H3 + r0 * HID + j] = q0;
                s[OFF_H3 + r1 * HID + j] = q1;
            }
            if (u + 1 <= TT - 1) {          // h1(u+1), my rows
                s[OFF_H1 + r0 * HID + j] = tanho(tblA + v1[r0] + o1.x);
                s[OFF_H1 + r1 * HID + j] = tanho(tblB + v1[r1] + o1.y);
            }
            if (u <= TT - 1) {              // h2(u)
                s[OFF_H2 + r0 * HID + j] = tanho(rb2 + v2[r0] + o2.x);
                s[OFF_H2 + r1 * HID + j] = tanho(rb2 + v2[r1] + o2.y);
            }
        }
        tokA = nA; tokB = nB;
        __syncthreads();
    }

    // ---- final hidden [NL, B, HID]: buffers hold h(TT-1) for all layers ----
    for (int i = tid; i < NL * ROWS * HID; i += NTHR) {
        const int l = i / (ROWS * HID);
        const int rem = i - l * (ROWS * HID);
        const int r = rem / HID;
        const int jj = rem - r * HID;
        hidden[(size_t)(l * BB + b0 + r) * HID + jj] =
            s[OFF_H1 + l * 400 + r * HID + jj];
    }
}

// ---------------------------------------------------------------------------
// Decoder GEMM (unchanged from R12/R14)
// ---------------------------------------------------------------------------
#define DT   256
#define GR   128
#define DS_W 0
#define DS_H 6208
#define DS_B 19008
#define DS_FLOATS 19072

__global__ __launch_bounds__(DT)
void dec_kernel(const float* __restrict__ W_dec,
                const float* __restrict__ b_dec,
                float* __restrict__ logits) {
    extern __shared__ float ds[];
    const int tid  = threadIdx.x;
    const int tile = blockIdx.x;

    float4* sw4 = reinterpret_cast<float4*>(ds + DS_W);
    const float4* wsrc = reinterpret_cast<const float4*>(W_dec);
    for (int i = tid; i < VOCAB * HID / 4; i += DT) sw4[i] = wsrc[i];

    float4* sh4 = reinterpret_cast<float4*>(ds + DS_H);
    const float4* hsrc = reinterpret_cast<const float4*>(g_h3 + (size_t)tile * GR * HID);
    for (int i = tid; i < GR * HID / 4; i += DT) sh4[i] = hsrc[i];

    for (int i = tid; i < VOCAB; i += DT) ds[DS_B + i] = b_dec[i];
    __syncthreads();

    const int r    = tid & 127;
    const int half = tid >> 7;
    const int jb   = half * 31;

    ull acc[31];
#pragma unroll
    for (int jj = 0; jj < 31; jj++) acc[jj] = 0ull;

    const float* hrow = ds + DS_H + r * HID;
    for (int kc = 0; kc < 25; kc++) {
        ulonglong2 hq = ldv(hrow + 4 * kc);
#pragma unroll
        for (int jj = 0; jj < 31; jj++) {
            ulonglong2 wq = ldv(ds + DS_W + (jb + jj) * HID + 4 * kc);
            fma2(acc[jj], wq.x, hq.x);
            fma2(acc[jj], wq.y, hq.y);
        }
    }

    float* out = logits + ((size_t)tile * GR + r) * VOCAB + jb;
#pragma unroll
    for (int jj = 0; jj < 31; jj++)
        out[jj] = ds[DS_B + jb + jj] + hadd2(acc[jj]);
}

// ---------------------------------------------------------------------------
extern "C" void kernel_launch(void* const* d_in, const int* in_sizes, int n_in,
                              void* d_out, int out_size) {
    const int*   ids   = (const int*)  d_in[0];
    const float* emb   = (const float*)d_in[1];
    const float* W_ih  = (const float*)d_in[2];
    const float* W_hh  = (const float*)d_in[3];
    const float* b_ih  = (const float*)d_in[4];
    const float* b_hh  = (const float*)d_in[5];
    const float* W_dec = (const float*)d_in[6];
    const float* b_dec = (const float*)d_in[7];

    float* out    = (float*)d_out;
    float* logits = out;
    float* hidden = out + ((size_t)out_size - (size_t)NL * BB * HID);

    table_kernel<<<VOCAB, 128>>>(emb, W_ih, b_ih, b_hh);

    size_t smem = SMEM_FLOATS * sizeof(float);
    cudaFuncSetAttribute(rnn_kernel, cudaFuncAttributeMaxDynamicSharedMemorySize,
                         (int)smem);
    rnn_kernel<<<NCTA, NTHR, smem>>>(ids, W_ih, W_hh, b_ih, b_hh, hidden);

    size_t dsmem = DS_FLOATS * sizeof(float);
    cudaFuncSetAttribute(dec_kernel, cudaFuncAttributeMaxDynamicSharedMemorySize,
                         (int)dsmem);
    dec_kernel<<<(BB * TT) / GR, DT, dsmem>>>(W_dec, b_dec, logits);
}